// round 5
// baseline (speedup 1.0000x reference)
#include <cuda_runtime.h>
#include <cstdint>

#define N1 8112
#define N2 2028
#define N3 507
#define NANCH 10647
#define NB 8
#define NC 80
#define KTOP 256
#define MAXPC 100
#define MAXTOT 100
#define SCORE_THR 0.3f
#define IOU_THR 0.5f
#define NEGV -1000000000.0f
#define PTHR 0.74f
#define CMAX 1024

__device__ unsigned long long g_cand[NB][NC][CMAX];   // 5.2 MB
__device__ int    g_ccnt[NB][NC];
__device__ float  g_sc[NB][NC * MAXPC];
__device__ float4 g_box[NB][NC * MAXPC];
__device__ int    g_cnt[NB][NC];

// ---------------------------------------------------------------------------
// Kernel -1: zero candidate counters (graph-replayed each call)
// ---------------------------------------------------------------------------
__global__ void init_kernel()
{
    int t = threadIdx.x;
    if (t < NB * NC) ((int*)g_ccnt)[t] = 0;
}

// ---------------------------------------------------------------------------
// Kernel 0: producer — scores > PTHR appended to per-(b,c) global lists.
// flat = anchor*20 + quad ; each thread: 1 conf load, maybe 1 float4 p load.
// ---------------------------------------------------------------------------
__global__ __launch_bounds__(256) void score_scan_kernel(
    const float* __restrict__ c1, const float* __restrict__ p1,
    const float* __restrict__ c2, const float* __restrict__ p2,
    const float* __restrict__ c3, const float* __restrict__ p3)
{
    const int b = blockIdx.y;
    int flat = blockIdx.x * 256 + threadIdx.x;
    if (flat >= NANCH * 20) return;
    int a = flat / 20;
    int q = flat - a * 20;

    const float* pp; const float* cc; int o;
    if (a < N1)           { pp = p1; cc = c1; o = b * N1 + a; }
    else if (a < N1 + N2) { pp = p2; cc = c2; o = b * N2 + (a - N1); }
    else                  { pp = p3; cc = c3; o = b * N3 + (a - N1 - N2); }

    float cf = __ldg(cc + o);
    if (cf <= PTHR) return;               // s = cf*cls <= cf : cannot pass

    float4 v = *reinterpret_cast<const float4*>(pp + (size_t)o * NC + q * 4);
    float sv[4] = {v.x * cf, v.y * cf, v.z * cf, v.w * cf};
#pragma unroll
    for (int k = 0; k < 4; k++) {
        float s = sv[k];
        if (s > PTHR) {
            int c = q * 4 + k;
            int pos = atomicAdd(&g_ccnt[b][c], 1);
            if (pos < CMAX)
                g_cand[b][c][pos] =
                    ((unsigned long long)__float_as_uint(s) << 32)
                    | (unsigned)(~(unsigned)a);
        }
    }
}

// ---------------------------------------------------------------------------
// Kernel 1: per-(image,class) NMS. Loads tiny candidate list, sorts, NMS.
// ---------------------------------------------------------------------------
__global__ __launch_bounds__(256) void nms_class_kernel(
    const float* __restrict__ b1, const float* __restrict__ b2,
    const float* __restrict__ b3,
    const float* __restrict__ c1, const float* __restrict__ p1,
    const float* __restrict__ c2, const float* __restrict__ p2,
    const float* __restrict__ c3, const float* __restrict__ p3)
{
    __shared__ unsigned long long keys[CMAX];      // 8 KB
    __shared__ float cy1[KTOP], cx1[KTOP], cy2[KTOP], cx2[KTOP];
    __shared__ float carea[KTOP], csc[KTOP];
    __shared__ int   keptslot[KTOP];
    __shared__ __align__(16) unsigned supp2[KTOP * 4];   // 4 KB fast path
    __shared__ __align__(16) unsigned supp8[KTOP * 8];   // 8 KB slow path
    __shared__ int hist[256];
    __shared__ int misc[8];
    __shared__ unsigned validm[8];

    const int b    = blockIdx.x / NC;
    const int c    = blockIdx.x % NC;
    const int tid  = threadIdx.x;
    const int lane = tid & 31;
    const unsigned ltmask = (1u << lane) - 1u;

    if (tid == 0) misc[4] = g_ccnt[b][c];
    __syncthreads();
    const int cnt = misc[4];

    int sortN;
    if (cnt >= KTOP && cnt <= CMAX) {
        // ---- good path: load candidate list (covers exact top-256) ----
        sortN = (cnt <= 512) ? 512 : CMAX;
#pragma unroll
        for (int k = 0; k < CMAX / 256; k++) {
            int i = tid + k * 256;
            keys[i] = (i < cnt) ? g_cand[b][c][i] : 0ull;
        }
        __syncthreads();
    } else {
        // ---- fallback (never taken for this data): strided full scan ----
        sortN = 512;
        hist[tid] = 0;
        if (tid == 0) { misc[0] = 0; misc[2] = 0; }
#pragma unroll
        for (int k = 0; k < CMAX / 256; k++) keys[tid + k * 256] = 0ull;
        __syncthreads();
        for (int a = tid; a < NANCH; a += 256) {
            const float* pp; const float* cc; int o;
            if (a < N1)           { pp = p1; cc = c1; o = b * N1 + a; }
            else if (a < N1 + N2) { pp = p2; cc = c2; o = b * N2 + (a - N1); }
            else                  { pp = p3; cc = c3; o = b * N3 + (a - N1 - N2); }
            float s = cc[o] * pp[(size_t)o * NC + c];
            if (s > SCORE_THR) {
                int bk = (int)((s - SCORE_THR) * (256.0f / 0.7f));
                bk = bk > 255 ? 255 : (bk < 0 ? 0 : bk);
                atomicAdd(&hist[bk], 1);
                atomicAdd(&misc[0], 1);
            }
        }
        __syncthreads();
        if (tid == 0) {
            int total = misc[0];
            int bb = 0;
            if (total >= KTOP) {
                int acc = 0;
                for (int i = 255; i >= 0; --i) {
                    acc += hist[i];
                    if (acc >= KTOP) { bb = i; break; }
                }
            }
            misc[1] = bb;
        }
        __syncthreads();
        const int bbv = misc[1];
        for (int a0 = 0; a0 < NANCH; a0 += 256) {
            int a = a0 + tid;
            float s = 0.0f;
            bool pred = false;
            if (a < NANCH) {
                const float* pp; const float* cc; int o;
                if (a < N1)           { pp = p1; cc = c1; o = b * N1 + a; }
                else if (a < N1 + N2) { pp = p2; cc = c2; o = b * N2 + (a - N1); }
                else                  { pp = p3; cc = c3; o = b * N3 + (a - N1 - N2); }
                s = cc[o] * pp[(size_t)o * NC + c];
                if (s > SCORE_THR) {
                    int bk = (int)((s - SCORE_THR) * (256.0f / 0.7f));
                    bk = bk > 255 ? 255 : (bk < 0 ? 0 : bk);
                    pred = (bk >= bbv);
                }
            }
            unsigned m = __ballot_sync(0xFFFFFFFFu, pred);
            if (pred) {
                int rank = __popc(m & ltmask);
                int base;
                if (rank == 0) base = atomicAdd(&misc[2], __popc(m));
                base = __shfl_sync(m, base, __ffs(m) - 1);
                int pos = base + rank;
                if (pos < 512)
                    keys[pos] = ((unsigned long long)__float_as_uint(s) << 32)
                                | (unsigned)(~(unsigned)a);
            }
        }
        __syncthreads();
    }

    // ---- bitonic sort sortN descending ----
    for (int k = 2; k <= sortN; k <<= 1) {
        for (int j = k >> 1; j > 0; j >>= 1) {
            for (int v = tid; v < (sortN >> 1); v += 256) {
                int i = ((v & ~(j - 1)) << 1) | (v & (j - 1));
                int p = i | j;
                unsigned long long va = keys[i], vb = keys[p];
                if ((va < vb) == ((i & k) == 0)) { keys[i] = vb; keys[p] = va; }
            }
            __syncthreads();
        }
    }

    // ---- top-256 -> SoA boxes/scores/areas/valid ----
    unsigned long long mykey = keys[tid];
    bool valid = (mykey != 0ull);
    float sc = __uint_as_float((unsigned)(mykey >> 32));
    float4 bx = make_float4(0.f, 0.f, 0.f, 0.f);
    if (valid) {
        unsigned a = ~(unsigned)(mykey & 0xFFFFFFFFu);
        const float* bp; size_t off;
        if (a < N1)           { bp = b1; off = (size_t)(b * N1 + a) * 4; }
        else if (a < N1 + N2) { bp = b2; off = (size_t)(b * N2 + (a - N1)) * 4; }
        else                  { bp = b3; off = (size_t)(b * N3 + (a - N1 - N2)) * 4; }
        bx = *reinterpret_cast<const float4*>(bp + off);
    }
    cy1[tid] = bx.x; cx1[tid] = bx.y; cy2[tid] = bx.z; cx2[tid] = bx.w;
    carea[tid] = (bx.z - bx.x) * (bx.w - bx.y);
    csc[tid] = sc;
    keptslot[tid] = -1;
    {
        unsigned bal = __ballot_sync(0xFFFFFFFFu, valid);
        if (lane == 0) validm[tid >> 5] = bal;
    }
    __syncthreads();

    // ---- 128x128 triangle, 2 threads per row ----
    {
        const int i = tid & 127;
        const int h = tid >> 7;
        const float y1 = cy1[i], x1 = cx1[i], y2 = cy2[i], x2 = cx2[i];
        const float areai = carea[i];
        unsigned w0 = 0u, w1 = 0u, w2 = 0u, w3 = 0u;
        for (int j = i + 1 + h; j < 128; j += 2) {
            float jy1 = cy1[j], jx1 = cx1[j], jy2 = cy2[j], jx2 = cx2[j];
            float aj = carea[j];
            float iy = fmaxf(fminf(y2, jy2) - fmaxf(y1, jy1), 0.0f);
            float ix = fmaxf(fminf(x2, jx2) - fmaxf(x1, jx1), 0.0f);
            float inter = iy * ix;
            float uni = (areai + aj) - inter;
            if (inter > 0.4f * uni) {          // exact-safe div filter
                float iou = inter / uni;
                if (iou > IOU_THR) {
                    unsigned bit = 1u << (j & 31);
                    switch (j >> 5) {
                        case 0: w0 |= bit; break; case 1: w1 |= bit; break;
                        case 2: w2 |= bit; break; default: w3 |= bit; break;
                    }
                }
            }
        }
        *reinterpret_cast<uint4*>(&supp2[tid * 4]) = make_uint4(w0, w1, w2, w3);
    }
    __syncthreads();

    // ---- fast serial scan over i<128, early stop at count==100 ----
    if (tid == 0) {
        unsigned k0 = validm[0], k1 = validm[1], k2 = validm[2], k3 = validm[3];
        int count = 0;
        bool hit = false;
        for (int w = 0; w < 4 && !hit; w++) {
            unsigned kw = (w == 0) ? k0 : (w == 1) ? k1 : (w == 2) ? k2 : k3;
            unsigned cw = kw;
            while (cw) {
                int bit = __ffs(cw) - 1;
                int i = (w << 5) + bit;
                count++;
                keptslot[i] = count - 1;
                if (count == MAXPC) { hit = true; break; }
                uint4 ra = *reinterpret_cast<const uint4*>(&supp2[i * 4]);
                uint4 rb = *reinterpret_cast<const uint4*>(&supp2[(i + 128) * 4]);
                k0 &= ~(ra.x | rb.x); k1 &= ~(ra.y | rb.y);
                k2 &= ~(ra.z | rb.z); k3 &= ~(ra.w | rb.w);
                unsigned above = (bit == 31) ? 0u : (0xFFFFFFFFu << (bit + 1));
                kw = (w == 0) ? k0 : (w == 1) ? k1 : (w == 2) ? k2 : k3;
                cw = kw & above;
            }
        }
        misc[3] = hit ? 1 : 0;
        if (hit) { misc[2] = MAXPC; g_cnt[b][c] = MAXPC; }
    }
    __syncthreads();

    // ---- slow path (rare): full 256x256 matrix + full rescan ----
    if (!misc[3]) {
        const int i = tid;
        const float y1 = cy1[i], x1 = cx1[i], y2 = cy2[i], x2 = cx2[i];
        const float areai = carea[i];
        unsigned words[8];
#pragma unroll
        for (int w = 0; w < 8; w++) words[w] = 0u;
        for (int j = i + 1; j < KTOP; j++) {
            float jy1 = cy1[j], jx1 = cx1[j], jy2 = cy2[j], jx2 = cx2[j];
            float aj = carea[j];
            float iy = fmaxf(fminf(y2, jy2) - fmaxf(y1, jy1), 0.0f);
            float ix = fmaxf(fminf(x2, jx2) - fmaxf(x1, jx1), 0.0f);
            float inter = iy * ix;
            float uni = (areai + aj) - inter;
            if (inter > 0.4f * uni) {
                float iou = inter / uni;
                if (iou > IOU_THR) words[j >> 5] |= (1u << (j & 31));
            }
        }
        uint4* sp = reinterpret_cast<uint4*>(&supp8[i * 8]);
        sp[0] = make_uint4(words[0], words[1], words[2], words[3]);
        sp[1] = make_uint4(words[4], words[5], words[6], words[7]);
        __syncthreads();
        if (tid == 0) {
            unsigned kk[8];
#pragma unroll
            for (int w = 0; w < 8; w++) kk[w] = validm[w];
            int count = 0;
            for (int w = 0; w < 8; w++) {
                unsigned cw = kk[w];
                while (cw) {
                    int bit = __ffs(cw) - 1;
                    int i2 = (w << 5) + bit;
                    count++;
                    if (count <= MAXPC) keptslot[i2] = count - 1;
                    uint4 r0 = *reinterpret_cast<const uint4*>(&supp8[i2 * 8]);
                    uint4 r1 = *reinterpret_cast<const uint4*>(&supp8[i2 * 8 + 4]);
                    kk[0] &= ~r0.x; kk[1] &= ~r0.y; kk[2] &= ~r0.z; kk[3] &= ~r0.w;
                    kk[4] &= ~r1.x; kk[5] &= ~r1.y; kk[6] &= ~r1.z; kk[7] &= ~r1.w;
                    unsigned above = (bit == 31) ? 0u : (0xFFFFFFFFu << (bit + 1));
                    cw = kk[w] & above;
                }
            }
            int cc2 = count > MAXPC ? MAXPC : count;
            misc[2] = cc2;
            g_cnt[b][c] = cc2;
        }
        __syncthreads();
    }

    // ---- epilogue: kept writes + NEG tail ----
    {
        int r = keptslot[tid];
        if (r >= 0 && r < MAXPC) {
            g_sc[b][c * MAXPC + r]  = csc[tid];
            g_box[b][c * MAXPC + r] = bx;
        }
        int cf = misc[2];
        if (tid >= cf && tid < MAXPC) g_sc[b][c * MAXPC + tid] = NEGV;
    }
}

// ---------------------------------------------------------------------------
// Kernel 2: per-image top-100, prefiltered histogram + small sort.
// ---------------------------------------------------------------------------
#define FBINS 2048
#define FCAND 512

__global__ __launch_bounds__(256) void topk_final_kernel(float* __restrict__ out)
{
    __shared__ int hist2[FBINS];
    __shared__ unsigned long long keys2[FCAND];
    __shared__ int gsum[64];
    __shared__ int misc2[8];
    __shared__ float s_lo;

    const int b   = blockIdx.x;
    const int tid = threadIdx.x;

    keys2[tid] = 0ull;
    keys2[tid + 256] = 0ull;
    if (tid == 0) { misc2[0] = 0; misc2[2] = 0; s_lo = 0.95f; misc2[3] = 0; }
    __syncthreads();
    if (tid < NC) atomicAdd(&misc2[2], g_cnt[b][tid]);

    const float4* gs4 = reinterpret_cast<const float4*>(&g_sc[b][0]);

    // up to 2 attempts: lo=0.95 then lo=0.3 (uniform control flow via smem)
    for (int attempt = 0; attempt < 2; attempt++) {
        if (misc2[3]) break;           // done flag (uniform)
        float lo = s_lo;
        float scale = (float)FBINS / (1.0f - lo);
#pragma unroll
        for (int k = 0; k < 8; k++) hist2[tid + k * 256] = 0;
        __syncthreads();
#pragma unroll
        for (int k = 0; k < 8; k++) {
            int t = tid + k * 256;
            if (t < (NC * MAXPC) / 4) {
                float4 v = gs4[t];
                float sv[4] = {v.x, v.y, v.z, v.w};
#pragma unroll
                for (int q = 0; q < 4; q++) {
                    float s = sv[q];
                    if (s > lo) {
                        int bk = (int)((s - lo) * scale);
                        bk = bk > FBINS - 1 ? FBINS - 1 : (bk < 0 ? 0 : bk);
                        atomicAdd(&hist2[bk], 1);
                    }
                }
            }
        }
        __syncthreads();
        if (tid < 64) {
            int s = 0;
#pragma unroll
            for (int k = 0; k < 32; k++) s += hist2[tid * 32 + k];
            gsum[tid] = s;
        }
        __syncthreads();
        if (tid == 0) {
            int total = 0;
            for (int i = 0; i < 64; i++) total += gsum[i];
            if (total >= MAXTOT || lo <= SCORE_THR + 1e-6f) {
                int acc = 0, g = -1, bbv = 0;
                for (int i = 63; i >= 0; i--) {
                    if (acc + gsum[i] >= MAXTOT) { g = i; break; }
                    acc += gsum[i];
                }
                if (g >= 0) {
                    for (int k = 31; k >= 0; k--) {
                        acc += hist2[g * 32 + k];
                        if (acc >= MAXTOT) { bbv = g * 32 + k; break; }
                    }
                }
                misc2[1] = bbv;
                misc2[3] = 1;
            } else {
                s_lo = SCORE_THR;
            }
        }
        __syncthreads();
    }

    const float lo = s_lo;
    const float scale = (float)FBINS / (1.0f - lo);
    const int bb = misc2[1];
#pragma unroll
    for (int k = 0; k < 8; k++) {
        int t = tid + k * 256;
        if (t < (NC * MAXPC) / 4) {
            float4 v = gs4[t];
            float sv[4] = {v.x, v.y, v.z, v.w};
#pragma unroll
            for (int q = 0; q < 4; q++) {
                float s = sv[q];
                if (s > lo) {
                    int bk = (int)((s - lo) * scale);
                    bk = bk > FBINS - 1 ? FBINS - 1 : (bk < 0 ? 0 : bk);
                    if (bk >= bb) {
                        int pos = atomicAdd(&misc2[0], 1);
                        if (pos < FCAND) {
                            unsigned s_idx = (unsigned)(t * 4 + q);
                            keys2[pos] = ((unsigned long long)__float_as_uint(s) << 32)
                                         | (unsigned)(~s_idx);
                        }
                    }
                }
            }
        }
    }
    __syncthreads();

    for (int k = 2; k <= FCAND; k <<= 1) {
        for (int j = k >> 1; j > 0; j >>= 1) {
            int i = ((tid & ~(j - 1)) << 1) | (tid & (j - 1));
            int p = i | j;
            unsigned long long va = keys2[i], vb = keys2[p];
            if ((va < vb) == ((i & k) == 0)) { keys2[i] = vb; keys2[p] = va; }
            __syncthreads();
        }
    }

    float* ob = out;
    float* os = out + NB * MAXTOT * 4;
    float* oc = os + NB * MAXTOT;
    float* on = oc + NB * MAXTOT;

    if (tid < MAXTOT) {
        unsigned long long key = keys2[tid];
        float sc = 0.0f, cl = 0.0f;
        float bx0 = 0.f, bx1 = 0.f, bx2 = 0.f, bx3 = 0.f;
        if (key != 0ull) {
            sc = __uint_as_float((unsigned)(key >> 32));
            unsigned s = ~(unsigned)(key & 0xFFFFFFFFu);
            cl = (float)(s / MAXPC);
            float4 bbx = g_box[b][s];
            bx0 = fminf(fmaxf(bbx.x, 0.0f), 1.0f);
            bx1 = fminf(fmaxf(bbx.y, 0.0f), 1.0f);
            bx2 = fminf(fmaxf(bbx.z, 0.0f), 1.0f);
            bx3 = fminf(fmaxf(bbx.w, 0.0f), 1.0f);
        }
        size_t base = (size_t)(b * MAXTOT + tid) * 4;
        ob[base + 0] = bx0; ob[base + 1] = bx1; ob[base + 2] = bx2; ob[base + 3] = bx3;
        os[b * MAXTOT + tid] = sc;
        oc[b * MAXTOT + tid] = cl;
    }
    if (tid == 0) {
        int tot = misc2[2];
        on[b] = (float)(tot > MAXTOT ? MAXTOT : tot);
    }
}

extern "C" void kernel_launch(void* const* d_in, const int* in_sizes, int n_in,
                              void* d_out, int out_size)
{
    const float* b1 = (const float*)d_in[0];
    const float* c1 = (const float*)d_in[1];
    const float* p1 = (const float*)d_in[2];
    const float* b2 = (const float*)d_in[3];
    const float* c2 = (const float*)d_in[4];
    const float* p2 = (const float*)d_in[5];
    const float* b3 = (const float*)d_in[6];
    const float* c3 = (const float*)d_in[7];
    const float* p3 = (const float*)d_in[8];

    init_kernel<<<1, NB * NC>>>();
    dim3 sgrid((NANCH * 20 + 255) / 256, NB);
    score_scan_kernel<<<sgrid, 256>>>(c1, p1, c2, p2, c3, p3);
    nms_class_kernel<<<NB * NC, 256>>>(b1, b2, b3,
                                       c1, p1, c2, p2, c3, p3);
    topk_final_kernel<<<NB, 256>>>((float*)d_out);
}

// round 6
// speedup vs baseline: 2.1662x; 2.1662x over previous
#include <cuda_runtime.h>
#include <cstdint>

#define N1 8112
#define N2 2028
#define N3 507
#define NANCH 10647
#define NANCH_P 10656
#define NVEC4 (NANCH_P / 4)        /* 2664 */
#define NB 8
#define NC 80
#define KTOP 256
#define CAND 512
#define MAXPC 100
#define MAXTOT 100
#define SCORE_THR 0.3f
#define IOU_THR 0.5f
#define NEGV -1000000000.0f
#define PTHR 0.74f
#define TTHR 0.978f
#define TILE_A 64

__device__ float  g_scoresT[NB][NC][NANCH_P];
__device__ float  g_sc[NB][NC * MAXPC];
__device__ float4 g_box[NB][NC * MAXPC];
__device__ int    g_cnt[NB][NC];

// ---------------------------------------------------------------------------
// Kernel 0: score compute + transpose. 128 threads, TILE_A=64 anchors/block.
// (unchanged from R4: measured 14.0us)
// ---------------------------------------------------------------------------
__global__ __launch_bounds__(128) void score_transpose_kernel(
    const float* __restrict__ c1, const float* __restrict__ p1,
    const float* __restrict__ c2, const float* __restrict__ p2,
    const float* __restrict__ c3, const float* __restrict__ p3)
{
    __shared__ float conf_s[TILE_A];
    __shared__ float tile[TILE_A][NC + 1];

    const int b   = blockIdx.y;
    const int t0  = blockIdx.x * TILE_A;
    const int tid = threadIdx.x;

    if (tid < TILE_A) {
        int a = t0 + tid;
        float cv = 0.0f;
        if (a < NANCH) {
            if (a < N1)           cv = c1[b * N1 + a];
            else if (a < N1 + N2) cv = c2[b * N2 + (a - N1)];
            else                  cv = c3[b * N3 + (a - N1 - N2)];
        }
        conf_s[tid] = cv;
    }
    __syncthreads();

#pragma unroll
    for (int k = 0; k < 10; k++) {
        int idx = tid + k * 128;
        int al = idx / 20;
        int q  = idx - al * 20;
        int a  = t0 + al;
        float4 v = make_float4(0.f, 0.f, 0.f, 0.f);
        if (a < NANCH) {
            const float* pp; int o;
            if (a < N1)           { pp = p1; o = b * N1 + a; }
            else if (a < N1 + N2) { pp = p2; o = b * N2 + (a - N1); }
            else                  { pp = p3; o = b * N3 + (a - N1 - N2); }
            v = *reinterpret_cast<const float4*>(pp + (size_t)o * NC + q * 4);
        }
        float cf = conf_s[al];
        tile[al][q * 4 + 0] = v.x * cf;
        tile[al][q * 4 + 1] = v.y * cf;
        tile[al][q * 4 + 2] = v.z * cf;
        tile[al][q * 4 + 3] = v.w * cf;
    }
    __syncthreads();

#pragma unroll
    for (int k = 0; k < 10; k++) {
        int idx = tid + k * 128;
        int c  = idx >> 4;
        int g  = idx & 15;
        int al = g * 4;
        int a0 = t0 + al;
        if (a0 < NANCH_P) {
            float4 v = make_float4(tile[al][c], tile[al + 1][c],
                                   tile[al + 2][c], tile[al + 3][c]);
            *reinterpret_cast<float4*>(&g_scoresT[b][c][a0]) = v;
        }
    }
}

// ---------------------------------------------------------------------------
// Kernel 1: per-(image,class) NMS. Fast path: fixed 0.74 prefilter.
// ---------------------------------------------------------------------------
__global__ __launch_bounds__(256) void nms_class_kernel(
    const float* __restrict__ b1, const float* __restrict__ b2,
    const float* __restrict__ b3)
{
    __shared__ unsigned long long keys[CAND];                 // 4 KB
    __shared__ float cy1[KTOP], cx1[KTOP], cy2[KTOP], cx2[KTOP];
    __shared__ float carea[KTOP], csc[KTOP];
    __shared__ int   keptslot[KTOP];
    __shared__ __align__(16) unsigned supp2[KTOP * 4];        // 4 KB
    __shared__ __align__(16) unsigned supp8[KTOP * 8];        // 8 KB slow path
    __shared__ int hist[256];
    __shared__ int misc[8];
    __shared__ unsigned validm[8];

    const int b    = blockIdx.x / NC;
    const int c    = blockIdx.x % NC;
    const int tid  = threadIdx.x;
    const int lane = tid & 31;
    const unsigned ltmask = (1u << lane) - 1u;

    if (tid == 0) { misc[0] = 0; }
    keys[tid] = 0ull;
    keys[tid + 256] = 0ull;
    __syncthreads();

    // Phase 1 (fast): prefilter s > 0.74, ballot-aggregated append
    const float4* srow4 = reinterpret_cast<const float4*>(&g_scoresT[b][c][0]);
#pragma unroll
    for (int k0 = 0; k0 < 11; k0++) {
        int it = tid + k0 * 256;
        float4 v = make_float4(0.f, 0.f, 0.f, 0.f);
        if (it < NVEC4) v = srow4[it];
        float sv[4] = {v.x, v.y, v.z, v.w};
#pragma unroll
        for (int k = 0; k < 4; k++) {
            float s = sv[k];
            bool pred = s > PTHR;
            unsigned m = __ballot_sync(0xFFFFFFFFu, pred);
            if (pred) {
                int rank = __popc(m & ltmask);
                int base;
                if (rank == 0) base = atomicAdd(&misc[0], __popc(m));
                base = __shfl_sync(m, base, __ffs(m) - 1);
                int pos = base + rank;
                unsigned a = (unsigned)(it * 4 + k);
                if (pos < CAND)
                    keys[pos] = ((unsigned long long)__float_as_uint(s) << 32)
                                | (unsigned)(~a);
            }
        }
    }
    __syncthreads();
    const int pcnt = misc[0];
    const bool good = (pcnt >= KTOP && pcnt <= CAND);

    // Fallback (never taken for this data): full histogram selection at 0.3
    if (!good) {
        hist[tid] = 0;
        if (tid == 0) { misc[1] = 0; misc[2] = 0; }
        keys[tid] = 0ull;
        keys[tid + 256] = 0ull;
        __syncthreads();
        for (int it = tid; it < NVEC4; it += 256) {
            float4 v = srow4[it];
            float sv[4] = {v.x, v.y, v.z, v.w};
#pragma unroll
            for (int k = 0; k < 4; k++) {
                float s = sv[k];
                if (s > SCORE_THR) {
                    int bk = (int)((s - SCORE_THR) * (256.0f / 0.7f));
                    bk = bk > 255 ? 255 : (bk < 0 ? 0 : bk);
                    atomicAdd(&hist[bk], 1);
                }
            }
        }
        __syncthreads();
        if (tid == 0) {
            int acc = 0, bbv = 0;
            for (int i = 255; i >= 0; --i) {
                acc += hist[i];
                if (acc >= KTOP) { bbv = i; break; }
            }
            misc[1] = bbv;
        }
        __syncthreads();
        const int bbv = misc[1];
        for (int it = tid; it < NVEC4; it += 256) {
            float4 v = srow4[it];
            float sv[4] = {v.x, v.y, v.z, v.w};
#pragma unroll
            for (int k = 0; k < 4; k++) {
                float s = sv[k];
                bool pred = false;
                if (s > SCORE_THR) {
                    int bk = (int)((s - SCORE_THR) * (256.0f / 0.7f));
                    bk = bk > 255 ? 255 : (bk < 0 ? 0 : bk);
                    pred = (bk >= bbv);
                }
                unsigned m = __ballot_sync(0xFFFFFFFFu, pred);
                if (pred) {
                    int rank = __popc(m & ltmask);
                    int base;
                    if (rank == 0) base = atomicAdd(&misc[2], __popc(m));
                    base = __shfl_sync(m, base, __ffs(m) - 1);
                    int pos = base + rank;
                    unsigned a = (unsigned)(it * 4 + k);
                    if (pos < CAND)
                        keys[pos] = ((unsigned long long)__float_as_uint(s) << 32)
                                    | (unsigned)(~a);
                }
            }
        }
        __syncthreads();
    }

    // Phase 4: bitonic sort 512 descending (256 comparators/stage)
    for (int k = 2; k <= CAND; k <<= 1) {
        for (int j = k >> 1; j > 0; j >>= 1) {
            int i = ((tid & ~(j - 1)) << 1) | (tid & (j - 1));
            int p = i | j;
            unsigned long long va = keys[i], vb = keys[p];
            if ((va < vb) == ((i & k) == 0)) { keys[i] = vb; keys[p] = va; }
            __syncthreads();
        }
    }

    // Phase 5: top-256 -> SoA boxes/scores/areas/valid
    unsigned long long mykey = keys[tid];
    bool valid = (mykey != 0ull);
    float sc = __uint_as_float((unsigned)(mykey >> 32));
    float4 bx = make_float4(0.f, 0.f, 0.f, 0.f);
    if (valid) {
        unsigned a = ~(unsigned)(mykey & 0xFFFFFFFFu);
        const float* bp; size_t off;
        if (a < N1)           { bp = b1; off = (size_t)(b * N1 + a) * 4; }
        else if (a < N1 + N2) { bp = b2; off = (size_t)(b * N2 + (a - N1)) * 4; }
        else                  { bp = b3; off = (size_t)(b * N3 + (a - N1 - N2)) * 4; }
        bx = *reinterpret_cast<const float4*>(bp + off);
    }
    cy1[tid] = bx.x; cx1[tid] = bx.y; cy2[tid] = bx.z; cx2[tid] = bx.w;
    carea[tid] = (bx.z - bx.x) * (bx.w - bx.y);
    csc[tid] = sc;
    keptslot[tid] = -1;
    {
        unsigned bal = __ballot_sync(0xFFFFFFFFu, valid);
        if (lane == 0) validm[tid >> 5] = bal;
    }
    __syncthreads();

    // Phase 6a: 128x128 triangle, 2 threads per row
    {
        const int i = tid & 127;
        const int h = tid >> 7;
        const float y1 = cy1[i], x1 = cx1[i], y2 = cy2[i], x2 = cx2[i];
        const float areai = carea[i];
        unsigned w0 = 0u, w1 = 0u, w2 = 0u, w3 = 0u;
        for (int j = i + 1 + h; j < 128; j += 2) {
            float jy1 = cy1[j], jx1 = cx1[j], jy2 = cy2[j], jx2 = cx2[j];
            float aj = carea[j];
            float iy = fmaxf(fminf(y2, jy2) - fmaxf(y1, jy1), 0.0f);
            float ix = fmaxf(fminf(x2, jx2) - fmaxf(x1, jx1), 0.0f);
            float inter = iy * ix;
            float uni = (areai + aj) - inter;
            if (inter > 0.4f * uni) {          // exact-safe div filter
                float iou = inter / uni;
                if (iou > IOU_THR) {
                    unsigned bit = 1u << (j & 31);
                    switch (j >> 5) {
                        case 0: w0 |= bit; break; case 1: w1 |= bit; break;
                        case 2: w2 |= bit; break; default: w3 |= bit; break;
                    }
                }
            }
        }
        *reinterpret_cast<uint4*>(&supp2[tid * 4]) = make_uint4(w0, w1, w2, w3);
    }
    __syncthreads();

    // Phase 7a: serial scan over i<128, early stop at count==100
    if (tid == 0) {
        unsigned k0 = validm[0], k1 = validm[1], k2 = validm[2], k3 = validm[3];
        int count = 0;
        bool hit = false;
        for (int w = 0; w < 4 && !hit; w++) {
            unsigned kw = (w == 0) ? k0 : (w == 1) ? k1 : (w == 2) ? k2 : k3;
            unsigned cw = kw;
            while (cw) {
                int bit = __ffs(cw) - 1;
                int i = (w << 5) + bit;
                count++;
                keptslot[i] = count - 1;
                if (count == MAXPC) { hit = true; break; }
                uint4 ra = *reinterpret_cast<const uint4*>(&supp2[i * 4]);
                uint4 rb = *reinterpret_cast<const uint4*>(&supp2[(i + 128) * 4]);
                k0 &= ~(ra.x | rb.x); k1 &= ~(ra.y | rb.y);
                k2 &= ~(ra.z | rb.z); k3 &= ~(ra.w | rb.w);
                unsigned above = (bit == 31) ? 0u : (0xFFFFFFFFu << (bit + 1));
                kw = (w == 0) ? k0 : (w == 1) ? k1 : (w == 2) ? k2 : k3;
                cw = kw & above;
            }
        }
        misc[3] = hit ? 1 : 0;
        if (hit) { misc[2] = MAXPC; g_cnt[b][c] = MAXPC; }
    }
    __syncthreads();

    // Slow path (rare): full 256x256 matrix + full rescan
    if (!misc[3]) {
        const int i = tid;
        const float y1 = cy1[i], x1 = cx1[i], y2 = cy2[i], x2 = cx2[i];
        const float areai = carea[i];
        unsigned words[8];
#pragma unroll
        for (int w = 0; w < 8; w++) words[w] = 0u;
        for (int j = i + 1; j < KTOP; j++) {
            float jy1 = cy1[j], jx1 = cx1[j], jy2 = cy2[j], jx2 = cx2[j];
            float aj = carea[j];
            float iy = fmaxf(fminf(y2, jy2) - fmaxf(y1, jy1), 0.0f);
            float ix = fmaxf(fminf(x2, jx2) - fmaxf(x1, jx1), 0.0f);
            float inter = iy * ix;
            float uni = (areai + aj) - inter;
            if (inter > 0.4f * uni) {
                float iou = inter / uni;
                if (iou > IOU_THR) words[j >> 5] |= (1u << (j & 31));
            }
        }
        uint4* sp = reinterpret_cast<uint4*>(&supp8[i * 8]);
        sp[0] = make_uint4(words[0], words[1], words[2], words[3]);
        sp[1] = make_uint4(words[4], words[5], words[6], words[7]);
        __syncthreads();
        if (tid == 0) {
            unsigned kk[8];
#pragma unroll
            for (int w = 0; w < 8; w++) kk[w] = validm[w];
            int count = 0;
            for (int w = 0; w < 8; w++) {
                unsigned cw = kk[w];
                while (cw) {
                    int bit = __ffs(cw) - 1;
                    int i2 = (w << 5) + bit;
                    count++;
                    if (count <= MAXPC) keptslot[i2] = count - 1;
                    uint4 r0 = *reinterpret_cast<const uint4*>(&supp8[i2 * 8]);
                    uint4 r1 = *reinterpret_cast<const uint4*>(&supp8[i2 * 8 + 4]);
                    kk[0] &= ~r0.x; kk[1] &= ~r0.y; kk[2] &= ~r0.z; kk[3] &= ~r0.w;
                    kk[4] &= ~r1.x; kk[5] &= ~r1.y; kk[6] &= ~r1.z; kk[7] &= ~r1.w;
                    unsigned above = (bit == 31) ? 0u : (0xFFFFFFFFu << (bit + 1));
                    cw = kk[w] & above;
                }
            }
            int cc2 = count > MAXPC ? MAXPC : count;
            misc[2] = cc2;
            g_cnt[b][c] = cc2;
        }
        __syncthreads();
    }

    // Epilogue: kept writes + NEG tail so topk can stream g_sc blindly
    {
        int r = keptslot[tid];
        if (r >= 0 && r < MAXPC) {
            g_sc[b][c * MAXPC + r]  = csc[tid];
            g_box[b][c * MAXPC + r] = bx;
        }
        int cf = misc[2];
        if (tid >= cf && tid < MAXPC) g_sc[b][c * MAXPC + tid] = NEGV;
    }
}

// ---------------------------------------------------------------------------
// Kernel 2: per-image top-100. Fast path: gather > 0.978, sort 256.
// ---------------------------------------------------------------------------
#define FBINS 2048
#define FCAND 512

__global__ __launch_bounds__(256) void topk_final_kernel(float* __restrict__ out)
{
    __shared__ int hist2[FBINS];
    __shared__ unsigned long long keys2[FCAND];
    __shared__ int gsum[64];
    __shared__ int misc2[8];

    const int b   = blockIdx.x;
    const int tid = threadIdx.x;
    const int lane = tid & 31;
    const unsigned ltmask = (1u << lane) - 1u;

    keys2[tid] = 0ull;
    keys2[tid + 256] = 0ull;
    if (tid == 0) { misc2[0] = 0; misc2[2] = 0; }
    __syncthreads();
    if (tid < NC) atomicAdd(&misc2[2], g_cnt[b][tid]);

    const float4* gs4 = reinterpret_cast<const float4*>(&g_sc[b][0]);

    // Fast gather: s > 0.978 (expected ~204 per image)
#pragma unroll
    for (int k = 0; k < 8; k++) {
        int t = tid + k * 256;
        float4 v = make_float4(NEGV, NEGV, NEGV, NEGV);
        if (t < (NC * MAXPC) / 4) v = gs4[t];
        float sv[4] = {v.x, v.y, v.z, v.w};
#pragma unroll
        for (int q = 0; q < 4; q++) {
            float s = sv[q];
            bool pred = s > TTHR;
            unsigned m = __ballot_sync(0xFFFFFFFFu, pred);
            if (pred) {
                int rank = __popc(m & ltmask);
                int base;
                if (rank == 0) base = atomicAdd(&misc2[0], __popc(m));
                base = __shfl_sync(m, base, __ffs(m) - 1);
                int pos = base + rank;
                if (pos < KTOP) {
                    unsigned s_idx = (unsigned)(t * 4 + q);
                    keys2[pos] = ((unsigned long long)__float_as_uint(s) << 32)
                                 | (unsigned)(~s_idx);
                }
            }
        }
    }
    __syncthreads();
    const int gcnt = misc2[0];
    const bool good = (gcnt >= MAXTOT && gcnt <= KTOP);
    int sortN = KTOP;

    if (!good) {
        // Fallback: histogram at 0.3, cut for top-100, gather into 512
        sortN = FCAND;
#pragma unroll
        for (int k = 0; k < 8; k++) hist2[tid + k * 256] = 0;
        keys2[tid] = 0ull;
        keys2[tid + 256] = 0ull;
        if (tid == 0) misc2[0] = 0;
        __syncthreads();
#pragma unroll
        for (int k = 0; k < 8; k++) {
            int t = tid + k * 256;
            if (t < (NC * MAXPC) / 4) {
                float4 v = gs4[t];
                float sv[4] = {v.x, v.y, v.z, v.w};
#pragma unroll
                for (int q = 0; q < 4; q++) {
                    float s = sv[q];
                    if (s > SCORE_THR) {
                        int bk = (int)((s - SCORE_THR) * ((float)FBINS / 0.7f));
                        bk = bk > FBINS - 1 ? FBINS - 1 : (bk < 0 ? 0 : bk);
                        atomicAdd(&hist2[bk], 1);
                    }
                }
            }
        }
        __syncthreads();
        if (tid < 64) {
            int s = 0;
#pragma unroll
            for (int k = 0; k < 32; k++) s += hist2[tid * 32 + k];
            gsum[tid] = s;
        }
        __syncthreads();
        if (tid == 0) {
            int acc = 0, g = -1, bbv = 0;
            for (int i = 63; i >= 0; i--) {
                if (acc + gsum[i] >= MAXTOT) { g = i; break; }
                acc += gsum[i];
            }
            if (g >= 0) {
                for (int k = 31; k >= 0; k--) {
                    acc += hist2[g * 32 + k];
                    if (acc >= MAXTOT) { bbv = g * 32 + k; break; }
                }
            }
            misc2[1] = bbv;
        }
        __syncthreads();
        const int bb = misc2[1];
#pragma unroll
        for (int k = 0; k < 8; k++) {
            int t = tid + k * 256;
            if (t < (NC * MAXPC) / 4) {
                float4 v = gs4[t];
                float sv[4] = {v.x, v.y, v.z, v.w};
#pragma unroll
                for (int q = 0; q < 4; q++) {
                    float s = sv[q];
                    if (s > SCORE_THR) {
                        int bk = (int)((s - SCORE_THR) * ((float)FBINS / 0.7f));
                        bk = bk > FBINS - 1 ? FBINS - 1 : (bk < 0 ? 0 : bk);
                        if (bk >= bb) {
                            int pos = atomicAdd(&misc2[0], 1);
                            if (pos < FCAND) {
                                unsigned s_idx = (unsigned)(t * 4 + q);
                                keys2[pos] =
                                    ((unsigned long long)__float_as_uint(s) << 32)
                                    | (unsigned)(~s_idx);
                            }
                        }
                    }
                }
            }
        }
        __syncthreads();
    }

    // bitonic sort sortN descending
    for (int k = 2; k <= sortN; k <<= 1) {
        for (int j = k >> 1; j > 0; j >>= 1) {
            for (int v = tid; v < (sortN >> 1); v += 256) {
                int i = ((v & ~(j - 1)) << 1) | (v & (j - 1));
                int p = i | j;
                unsigned long long va = keys2[i], vb = keys2[p];
                if ((va < vb) == ((i & k) == 0)) { keys2[i] = vb; keys2[p] = va; }
            }
            __syncthreads();
        }
    }

    float* ob = out;
    float* os = out + NB * MAXTOT * 4;
    float* oc = os + NB * MAXTOT;
    float* on = oc + NB * MAXTOT;

    if (tid < MAXTOT) {
        unsigned long long key = keys2[tid];
        float sc = 0.0f, cl = 0.0f;
        float bx0 = 0.f, bx1 = 0.f, bx2 = 0.f, bx3 = 0.f;
        if (key != 0ull) {
            sc = __uint_as_float((unsigned)(key >> 32));
            unsigned s = ~(unsigned)(key & 0xFFFFFFFFu);
            cl = (float)(s / MAXPC);
            float4 bbx = g_box[b][s];
            bx0 = fminf(fmaxf(bbx.x, 0.0f), 1.0f);
            bx1 = fminf(fmaxf(bbx.y, 0.0f), 1.0f);
            bx2 = fminf(fmaxf(bbx.z, 0.0f), 1.0f);
            bx3 = fminf(fmaxf(bbx.w, 0.0f), 1.0f);
        }
        size_t base = (size_t)(b * MAXTOT + tid) * 4;
        ob[base + 0] = bx0; ob[base + 1] = bx1; ob[base + 2] = bx2; ob[base + 3] = bx3;
        os[b * MAXTOT + tid] = sc;
        oc[b * MAXTOT + tid] = cl;
    }
    if (tid == 0) {
        int tot = misc2[2];
        on[b] = (float)(tot > MAXTOT ? MAXTOT : tot);
    }
}

extern "C" void kernel_launch(void* const* d_in, const int* in_sizes, int n_in,
                              void* d_out, int out_size)
{
    const float* b1 = (const float*)d_in[0];
    const float* c1 = (const float*)d_in[1];
    const float* p1 = (const float*)d_in[2];
    const float* b2 = (const float*)d_in[3];
    const float* c2 = (const float*)d_in[4];
    const float* p2 = (const float*)d_in[5];
    const float* b3 = (const float*)d_in[6];
    const float* c3 = (const float*)d_in[7];
    const float* p3 = (const float*)d_in[8];

    dim3 tgrid((NANCH + TILE_A - 1) / TILE_A, NB);
    score_transpose_kernel<<<tgrid, 128>>>(c1, p1, c2, p2, c3, p3);
    nms_class_kernel<<<NB * NC, 256>>>(b1, b2, b3);
    topk_final_kernel<<<NB, 256>>>((float*)d_out);
}